// round 17
// baseline (speedup 1.0000x reference)
#include <cuda_runtime.h>
#include <cuda_bf16.h>
#include <math_constants.h>

#define N_TOKENS   8192
#define QUANT_DIM  8192
#define OUTPUT_DIM 1024
#define SEC_COLS   32                       // one full 128B line per sector
#define N_SECTORS  (QUANT_DIM / SEC_COLS)   // 256
#define SLICE_ROWS 128
#define N_SLICES   (OUTPUT_DIM / SLICE_ROWS)   // 8
#define LIST_CHUNK 256

// Scratch (__device__ globals, zero-init at load). Invariant: gather resets
// g_cnt/g_done each run (fence-ordered after all readers) -> every graph
// replay starts clean.
__device__ int g_cnt[N_SECTORS];
__device__ int g_done[N_SECTORS];
__device__ int g_list[(size_t)N_SECTORS * N_TOKENS];   // packed (row<<5)|off

// ---------------------------------------------------------------------------
// Primary: streaming argmax, one block per row (jnp first-index tie-break).
// Each block ALSO prefetches its 4KB chunk of W into L2 (8192 blocks x 4KB
// = all 32MB), spreading W's DRAM read across the whole primary where ~20%
// spare bandwidth exists -- so the PDL gather later reads W at L2-hit rates.
// ---------------------------------------------------------------------------
__global__ __launch_bounds__(256) void argmax_rows_kernel(
    const float* __restrict__ x, const float* __restrict__ W)
{
#if __CUDA_ARCH__ >= 900
    cudaTriggerProgrammaticLaunchCompletion();
#endif
    const int row = blockIdx.x;

    // L2 prefetch of W chunk [row*4KB .. +4KB): 32 x 128B lines, lanes 0..31.
    if (threadIdx.x < 32) {
        const char* p = reinterpret_cast<const char*>(W)
                      + (size_t)row * 4096 + threadIdx.x * 128;
        asm volatile("prefetch.global.L2 [%0];" :: "l"(p));
    }

    const float4* __restrict__ xr =
        reinterpret_cast<const float4*>(x + (size_t)row * QUANT_DIM);

    float best = -CUDART_INF_F;
    int   bidx = 0;

    #pragma unroll
    for (int it = 0; it < 8; ++it) {
        const int i = threadIdx.x + it * 256;
        const float4 v = __ldcs(&xr[i]);           // streaming: keep W in L2
        const float vm = fmaxf(fmaxf(v.x, v.y), fmaxf(v.z, v.w));
        if (vm > best) {                            // rare after warmup
            best = vm;
            const int base = i * 4;
            bidx = (v.x == vm) ? base
                 : (v.y == vm) ? base + 1
                 : (v.z == vm) ? base + 2
                 :               base + 3;          // first-equal = first index
        }
    }

    #pragma unroll
    for (int off = 16; off > 0; off >>= 1) {
        float ov = __shfl_down_sync(0xFFFFFFFFu, best, off);
        int   oi = __shfl_down_sync(0xFFFFFFFFu, bidx, off);
        if (ov > best || (ov == best && oi < bidx)) { best = ov; bidx = oi; }
    }

    __shared__ float s_val[8];
    __shared__ int   s_idx[8];
    const int lane = threadIdx.x & 31;
    const int warp = threadIdx.x >> 5;
    if (lane == 0) { s_val[warp] = best; s_idx[warp] = bidx; }
    __syncthreads();

    if (warp == 0) {
        best = (lane < 8) ? s_val[lane] : -CUDART_INF_F;
        bidx = (lane < 8) ? s_idx[lane] : 0x7FFFFFFF;
        #pragma unroll
        for (int off = 4; off > 0; off >>= 1) {
            float ov = __shfl_down_sync(0xFFFFFFFFu, best, off);
            int   oi = __shfl_down_sync(0xFFFFFFFFu, bidx, off);
            if (ov > best || (ov == best && oi < bidx)) { best = ov; bidx = oi; }
        }
        if (lane == 0) {
            const int sec  = bidx >> 5;
            const int slot = atomicAdd(&g_cnt[sec], 1);
            g_list[((size_t)sec << 13) + slot] = (row << 5) | (bidx & 31);
        }
    }
}

// ---------------------------------------------------------------------------
// Secondary (PDL): block (sec, slice) preloads its 128-row x 32-col W slice
// into smem (pre-sync; W should be L2-resident by now), then after
// cudaGridDependencySynchronize() stages the sector's token list and emits
// each token's 128-float chunk: conflict-free LDS (stride 33) + 512B
// coalesced streaming STG. 2048 blocks @ 17KB smem -> high occupancy,
// short post-sync critical path.
// Reset: per-sector done counter (8 arrivals); fence orders each block's
// cnt-read before its arrival, so the last arrival safely zeroes state.
// ---------------------------------------------------------------------------
__global__ __launch_bounds__(256) void sector_gather_kernel(
    const float* __restrict__ W, float* __restrict__ out)
{
    __shared__ float s_tile[SLICE_ROWS * 33];   // ~17 KB, stride-33
    __shared__ int   s_list[LIST_CHUNK];
    __shared__ int   s_cnt;

    const int sec   = blockIdx.x;
    const int slice = blockIdx.y;
    const int tid   = threadIdx.x;

    // ---- pre-sync: preload W slice (L2 hits; overlaps primary tail) ----
    #pragma unroll
    for (int it = 0; it < 4; ++it) {
        const int s  = tid + it * 256;          // 1024 float4 slots
        const int r  = s >> 3;                  // row in slice (0..127)
        const int k4 = s & 7;                   // float4 within 32-col row
        const float4 v = __ldcs(reinterpret_cast<const float4*>(
            W + (size_t)(slice * SLICE_ROWS + r) * QUANT_DIM
              + sec * SEC_COLS + k4 * 4));
        s_tile[r * 33 + k4 * 4 + 0] = v.x;
        s_tile[r * 33 + k4 * 4 + 1] = v.y;
        s_tile[r * 33 + k4 * 4 + 2] = v.z;
        s_tile[r * 33 + k4 * 4 + 3] = v.w;
    }

#if __CUDA_ARCH__ >= 900
    cudaGridDependencySynchronize();            // primary done + visible
#endif

    if (tid == 0) {
        const int c = g_cnt[sec];
        s_cnt = c;
        __threadfence();                        // cnt-read before arrival
        const int d = atomicAdd(&g_done[sec], 1);
        if (d == N_SLICES - 1) { g_cnt[sec] = 0; g_done[sec] = 0; }
    }
    __syncthreads();                            // tile + cnt ready

    const int cnt   = s_cnt;
    const int q     = tid >> 7;                 // 2 tokens per iteration
    const int c_loc = tid & 127;

    for (int base = 0; base < cnt; base += LIST_CHUNK) {
        const int chunk = min(cnt - base, LIST_CHUNK);
        if (tid < chunk)
            s_list[tid] = g_list[((size_t)sec << 13) + base + tid];
        __syncthreads();

        for (int t = q; t < chunk; t += 2) {
            const int e     = s_list[t];                  // smem broadcast
            const int token = e >> 5;
            const int off   = e & 31;
            const float val = s_tile[c_loc * 33 + off];   // conflict-free
            __stcs(&out[(size_t)token * OUTPUT_DIM
                        + slice * SLICE_ROWS + c_loc], val);  // 512B coalesced
        }
        __syncthreads();                        // s_list reuse guard
    }
}

// ---------------------------------------------------------------------------
extern "C" void kernel_launch(void* const* d_in, const int* in_sizes, int n_in,
                              void* d_out, int out_size)
{
    const float* x = (const float*)d_in[0];   // [8192, 8192] fp32
    const float* W = (const float*)d_in[1];   // [1024, 8192] fp32
    float* out = (float*)d_out;               // [8192, 1024] fp32

    argmax_rows_kernel<<<N_TOKENS, 256>>>(x, W);

    // Secondary with programmatic dependent launch.
    cudaLaunchConfig_t cfg = {};
    cfg.gridDim  = dim3(N_SECTORS, N_SLICES);
    cfg.blockDim = dim3(256);
    cfg.dynamicSmemBytes = 0;
    cfg.stream = 0;
    cudaLaunchAttribute attr[1];
    attr[0].id = cudaLaunchAttributeProgrammaticStreamSerialization;
    attr[0].val.programmaticStreamSerializationAllowed = 1;
    cfg.attrs = attr;
    cfg.numAttrs = 1;
    cudaLaunchKernelEx(&cfg, sector_gather_kernel, W, out);
}